// round 16
// baseline (speedup 1.0000x reference)
#include <cuda_runtime.h>
#include <math.h>

#define TS 512
#define BN 128
#define IND 32
#define HN 512
#define ON 8
#define PN 64

// FX[t,b,h] = sum_i Win[h,i]*x[t,b,i]  (134 MB scratch)
__device__ float g_fx[(size_t)TS * BN * HN];
// Wr in h-pair/j-pair interleaved layout: ulonglong2 at [j2*256 + hp] =
// ( W[h0][j], W[h1][j] | W[h0][j+1], W[h1][j+1] ),  h0=2*hp, j=2*j2.
__device__ float g_wr2[(size_t)HN * HN];

typedef unsigned long long ull;

__device__ __forceinline__ ull ffma2(ull a, ull b, ull c) {
    ull d; asm("fma.rn.f32x2 %0,%1,%2,%3;" : "=l"(d) : "l"(a), "l"(b), "l"(c)); return d;
}
__device__ __forceinline__ ull pk2(float x, float y) {
    ull d; asm("mov.b64 %0,{%1,%2};" : "=l"(d) : "f"(x), "f"(y)); return d;
}
__device__ __forceinline__ void unpk2(ull a, float& lo, float& hi) {
    asm("mov.b64 {%0,%1},%2;" : "=f"(lo), "=f"(hi) : "l"(a));
}

// ---------------------------------------------------------------------------
// Kernel 1: FX = x @ Win^T, strict sequential-k FMA chain (bit-locked).
// ---------------------------------------------------------------------------
__global__ void __launch_bounds__(512, 1)
fx_kernel(const float* __restrict__ x, const float* __restrict__ Win) {
    __shared__ __align__(16) float xs[64 * IND];
    const int tid = threadIdx.x;

    float w[32];
    const float4* wr4 = (const float4*)(Win + tid * IND);
#pragma unroll
    for (int k = 0; k < 8; k++) {
        float4 f = wr4[k];
        w[4 * k + 0] = f.x; w[4 * k + 1] = f.y;
        w[4 * k + 2] = f.z; w[4 * k + 3] = f.w;
    }

    const int pair0 = blockIdx.x * 64;
    ((float4*)xs)[tid] = ((const float4*)(x + (size_t)pair0 * IND))[tid];
    __syncthreads();

    float* outp = g_fx + (size_t)pair0 * HN + tid;
#pragma unroll 4
    for (int k = 0; k < 64; k++) {
        const float* xk = xs + k * IND;
        float acc = 0.0f;
#pragma unroll
        for (int i = 0; i < IND; i++) acc = __fmaf_rn(w[i], xk[i], acc);
        outp[(size_t)k * HN] = acc;
    }
}

// ---------------------------------------------------------------------------
// Kernel 2: Wr[h][j] via sequential-p chain (bit-locked), h/j-pair interleaved.
// ---------------------------------------------------------------------------
__global__ void __launch_bounds__(512, 1)
wr_kernel(const float* __restrict__ pin, const float* __restrict__ pout,
          const float* __restrict__ l) {
    __shared__ float lp[PN];
    const int h = blockIdx.x;
    const int j = threadIdx.x;
    if (j < PN) lp[j] = __fmul_rn(l[j], pin[h * PN + j]);
    __syncthreads();

    const float* pr = pout + j * PN;
    float acc = 0.0f;
#pragma unroll
    for (int p = 0; p < PN; p++) acc = __fmaf_rn(lp[p], pr[p], acc);

    const size_t q4 = (size_t)(j >> 1) * 256 + (h >> 1);
    g_wr2[q4 * 4 + (h & 1) + 2 * (j & 1)] = acc;
}

// ---------------------------------------------------------------------------
// Kernel 3: scan. One CTA = TWO batches (still CTA-local, zero cross-CTA
// sync). 512 threads; warp = 16 h-pairs x 2 batches, so the two batch
// halves of a warp load IDENTICAL Wr addresses -> coalescer dedup halves
// chip L2 traffic. One FFMA2 chain per thread (bit-exact order, proven).
// ---------------------------------------------------------------------------
__global__ void __launch_bounds__(512, 1)
snn_kernel(const float* __restrict__ Wout, float* __restrict__ out,
           float arg_ls, float arg_lm, float arg_ld,
           float rgain, float dtc, float tref)
{
    // rdup[parity][batch][j2]: duplicated (r,r) pairs; inner stride 257
    // (+16 B) so the two batches' broadcasts hit different banks.
    __shared__ __align__(16) ulonglong2 rdup[2][2][257];
    __shared__ __align__(16) float woutT_sh[HN * ON];   // Wout^T[h][o]
    __shared__ float part_y[128];

    const int tid = threadIdx.x;
    const int w   = tid >> 5, ln = tid & 31;
    const int hp  = w * 16 + (ln & 15);   // h-pair 0..255 (h0=2hp, h1=2hp+1)
    const int bb  = ln >> 4;              // batch half 0/1
    const int b   = blockIdx.x * 2 + bb;  // global batch of this thread

    const float ls  = expf(arg_ls);
    const float lm  = expf(arg_lm);
    const float ldc = expf(arg_ld);
    const float olm = 1.0f - lm;

    for (int i = tid; i < HN * ON; i += 512)
        woutT_sh[i] = Wout[(i & 7) * HN + (i >> 3)];
    // zero parity-0 r buffers (each thread its own slot)
    rdup[0][bb][hp] = make_ulonglong2(0ull, 0ull);

    // neuron state for (h0, h1) of batch b
    float I[2]   = {0.f, 0.f};
    float mem[2] = {0.f, 0.f};
    float s[2]   = {0.f, 0.f};
    float r[2]   = {0.f, 0.f};
    float tl[2]  = {-1.f, -1.f};

    const float2* fxp = (const float2*)(g_fx + (size_t)b * HN + 2 * hp);
    float2 fxc = fxp[0];

    const ulonglong2* wp = (const ulonglong2*)g_wr2;   // [j2*256 + hp]

    __syncthreads();

#pragma unroll 1
    for (int t = 0; t < TS; t++) {
        const int par = t & 1, pn = par ^ 1;
        const int tn = (t < TS - 1) ? t + 1 : t;
        const float2 fxn = fxp[(size_t)tn * (BN * HN / 2)];   // prefetch

        // ONE FFMA2 chain, sequential in j (bit-exact, proven R7..R15).
        // Lanes 0-15 and 16-31 load the same q address -> dedup to 2 wf.
        const ulonglong2* d = &rdup[par][bb][0];
        ull acc = 0ull;
#pragma unroll 8
        for (int j2 = 0; j2 < 256; j2++) {
            const ulonglong2 q  = wp[(size_t)j2 * 256 + hp];  // LDG.128 dedup
            const ulonglong2 rr = d[j2];                      // LDS.128 bcast
            acc = ffma2(q.x, rr.x, acc);
            acc = ffma2(q.y, rr.y, acc);
        }
        float rec[2], fxv[2];
        unpk2(acc, rec[0], rec[1]);
        fxv[0] = fxc.x; fxv[1] = fxc.y;

        const float ti = __fmul_rn(dtc, (float)t);
#pragma unroll
        for (int hh = 0; hh < 2; hh++) {
            I[hh] = __fadd_rn(__fadd_rn(__fmul_rn(ls, I[hh]), fxv[hh]), rec[hh]);
            const float notref = (ti > __fadd_rn(tl[hh], tref)) ? 1.0f : 0.0f;
            const float memn = __fmul_rn(__fmul_rn(notref,
                    __fadd_rn(__fmul_rn(lm, mem[hh]), __fmul_rn(olm, I[hh]))),
                    __fsub_rn(1.0f, s[hh]));
            r[hh] = __fadd_rn(__fmul_rn(ldc, r[hh]), __fmul_rn(rgain, s[hh]));
            const float snew = (__fsub_rn(memn, 1.0f) > 0.0f) ? 1.0f : 0.0f;
            tl[hh] = __fadd_rn(tl[hh], __fmul_rn(__fsub_rn(ti, tl[hh]), snew));
            mem[hh] = memn; s[hh] = snew;
        }
        fxc = fxn;

        // publish r(t) as dup pairs into parity pn: one STS.128 per thread
        rdup[pn][bb][hp] = make_ulonglong2(pk2(r[0], r[0]), pk2(r[1], r[1]));
        __syncthreads();   // r(t) visible; chain reads of rdup[par] complete

        // y partials: 128 threads, 64 per batch. Segment seg covers
        // h in [seg*64, seg*64+64) = j2 base seg<<5; float offset of r(h)
        // within a batch block = 2h. Same bits, same sum order as R6..R15.
        if (tid < 128) {
            const int bbx = tid >> 6, idx = tid & 63;
            const int o = idx & 7, seg = idx >> 3;
            const float* wq = woutT_sh + (seg << 6) * 8 + o;
            const float* rr = (const float*)&rdup[pn][bbx][seg << 5];
            float e0 = 0.0f, e1 = 0.0f;
#pragma unroll
            for (int hh = 0; hh < 64; hh += 2) {
                e0 = __fmaf_rn(wq[hh << 3],       rr[hh * 2],       e0);
                e1 = __fmaf_rn(wq[(hh + 1) << 3], rr[(hh + 1) * 2], e1);
            }
            part_y[tid] = e0 + e1;
        }
        __syncthreads();   // part_y visible
        if (tid < 16) {
            const int bbx = tid >> 3, o = tid & 7;
            const float* q = part_y + bbx * 64 + o;
            float v = ((q[0] + q[8]) + (q[16] + q[24])) +
                      ((q[32] + q[40]) + (q[48] + q[56]));
            out[((size_t)t * BN + blockIdx.x * 2 + bbx) * ON + o] = v;
        }
        // next step's publish targets rdup[par] (disjoint from y's rdup[pn]
        // reads, which complete before the publish-side __syncthreads) — safe.
    }
}

extern "C" void kernel_launch(void* const* d_in, const int* in_sizes, int n_in,
                              void* d_out, int out_size) {
    const float* x    = (const float*)d_in[0];
    const float* Win  = (const float*)d_in[1];
    const float* Wout = (const float*)d_in[2];
    const float* pin  = (const float*)d_in[3];
    const float* pout = (const float*)d_in[4];
    const float* l    = (const float*)d_in[5];
    float* out = (float*)d_out;

    const float arg_ls = (float)(-0.002 / 0.01);
    const float arg_lm = (float)(-0.002 / 0.02);
    const float arg_ld = (float)(-0.002 / 0.03);
    const float rgain  = (float)(0.002 / 0.03);
    const float dtc    = (float)0.002;
    const float tref   = (float)(5.0 * 0.002);

    fx_kernel<<<(TS * BN) / 64, 512>>>(x, Win);
    wr_kernel<<<HN, 512>>>(pin, pout, l);
    snn_kernel<<<BN / 2, 512>>>(Wout, out, arg_ls, arg_lm, arg_ld,
                                rgain, dtc, tref);
}

// round 17
// speedup vs baseline: 2.6031x; 2.6031x over previous
#include <cuda_runtime.h>
#include <math.h>

#define TS 512
#define BN 128
#define IND 32
#define HN 512
#define ON 8
#define PN 64

// FX[t,b,h] = sum_i Win[h,i]*x[t,b,i]  (134 MB scratch)
__device__ float g_fx[(size_t)TS * BN * HN];
// Wr j-interleaved (R6 champion layout): float4 at [(j>>2)*HN + h] =
// W[h][4(j>>2) .. 4(j>>2)+3]
__device__ float g_wri[(size_t)HN * HN];

// ---------------------------------------------------------------------------
// Kernel 1: FX = x @ Win^T, strict sequential-k FMA chain (bit-locked).
// ---------------------------------------------------------------------------
__global__ void __launch_bounds__(512, 1)
fx_kernel(const float* __restrict__ x, const float* __restrict__ Win) {
    __shared__ __align__(16) float xs[64 * IND];
    const int tid = threadIdx.x;

    float w[32];
    const float4* wr4 = (const float4*)(Win + tid * IND);
#pragma unroll
    for (int k = 0; k < 8; k++) {
        float4 f = wr4[k];
        w[4 * k + 0] = f.x; w[4 * k + 1] = f.y;
        w[4 * k + 2] = f.z; w[4 * k + 3] = f.w;
    }

    const int pair0 = blockIdx.x * 64;
    ((float4*)xs)[tid] = ((const float4*)(x + (size_t)pair0 * IND))[tid];
    __syncthreads();

    float* outp = g_fx + (size_t)pair0 * HN + tid;
#pragma unroll 4
    for (int k = 0; k < 64; k++) {
        const float* xk = xs + k * IND;
        float acc = 0.0f;
#pragma unroll
        for (int i = 0; i < IND; i++) acc = __fmaf_rn(w[i], xk[i], acc);
        outp[(size_t)k * HN] = acc;
    }
}

// ---------------------------------------------------------------------------
// Kernel 2: Wr[h][j] via sequential-p chain (bit-locked), j-interleaved
// exactly as the R6 champion. Block = one h, thread = one j.
// ---------------------------------------------------------------------------
__global__ void __launch_bounds__(512, 1)
wr_kernel(const float* __restrict__ pin, const float* __restrict__ pout,
          const float* __restrict__ l) {
    __shared__ float lp[PN];
    const int h = blockIdx.x;
    const int j = threadIdx.x;
    if (j < PN) lp[j] = __fmul_rn(l[j], pin[h * PN + j]);
    __syncthreads();

    const float* pr = pout + j * PN;
    float acc = 0.0f;
#pragma unroll
    for (int p = 0; p < PN; p++) acc = __fmaf_rn(lp[p], pr[p], acc);

    g_wri[((size_t)(j >> 2) * HN + h) * 4 + (j & 3)] = acc;
}

// ---------------------------------------------------------------------------
// Kernel 3: scan, TWO timesteps per Wr pass. One CTA = one batch, 512
// threads, thread = one h (R6 champion layout). Per double-step:
//   A = r_in(t) (published prev iter), B = r_in(t+1) (elementwise-exact),
//   one pass over Wr computes both dense sequential-j chains (bit-exact),
//   then pointwise t and t+1, y(t) from B, y(t+1) from A'=r_in(t+2).
// ---------------------------------------------------------------------------
__global__ void __launch_bounds__(512, 1)
snn_kernel(const float* __restrict__ Wout, float* __restrict__ out,
           float arg_ls, float arg_lm, float arg_ld,
           float rgain, float dtc, float tref)
{
    __shared__ __align__(16) float woutT_sh[HN * ON];  // Wout^T[h][o]
    __shared__ __align__(16) float A_sh[HN];           // r_in(t), then r_in(t+2)
    __shared__ __align__(16) float B_sh[HN];           // r_in(t+1)
    __shared__ float part_a[64], part_b[64];

    const int tid = threadIdx.x;
    const int b   = blockIdx.x;

    const float ls  = expf(arg_ls);
    const float lm  = expf(arg_lm);
    const float ldc = expf(arg_ld);
    const float olm = 1.0f - lm;

    for (int i = tid; i < HN * ON; i += 512) {
        int h = i >> 3, o = i & 7;
        woutT_sh[i] = Wout[o * HN + h];
    }
    A_sh[tid] = 0.0f;   // r_in(0) = 0

    float I = 0.0f, mem = 0.0f, s = 0.0f, r = 0.0f, tlast = -1.0f;

    const float* fxg = g_fx + (size_t)b * HN + tid;
    float fx0 = fxg[0];
    float fx1 = fxg[(size_t)(BN * HN)];

    const float4* wr4 = (const float4*)g_wri;   // [(j>>2)*HN + h]

    __syncthreads();

#pragma unroll 1
    for (int t = 0; t < TS; t += 2) {
        // phase 0: r_in(t+1) elementwise (EXACT reference op), publish B
        const float rn = __fadd_rn(__fmul_rn(ldc, r), __fmul_rn(rgain, s));
        B_sh[tid] = rn;
        __syncthreads();   // A (r_in(t)) and B (r_in(t+1)) ready

        // prefetch fx(t+2), fx(t+3) (clamped on last iter; values unused then)
        const int i2 = (t + 2 < TS) ? t + 2 : t;
        const int i3 = (t + 2 < TS) ? t + 3 : t + 1;
        const float fx2 = fxg[(size_t)i2 * (BN * HN)];
        const float fx3 = fxg[(size_t)i3 * (BN * HN)];

        // ONE pass over Wr row h: two sequential-j scalar chains (bit-exact)
        float acc_a = 0.0f, acc_b = 0.0f;
#pragma unroll 8
        for (int j4 = 0; j4 < HN / 4; j4++) {
            const float4 q  = wr4[(size_t)j4 * HN + tid];  // coalesced LDG.128
            const float4 va = ((const float4*)A_sh)[j4];   // broadcast LDS.128
            const float4 vb = ((const float4*)B_sh)[j4];   // broadcast LDS.128
            acc_a = __fmaf_rn(q.x, va.x, acc_a);
            acc_a = __fmaf_rn(q.y, va.y, acc_a);
            acc_a = __fmaf_rn(q.z, va.z, acc_a);
            acc_a = __fmaf_rn(q.w, va.w, acc_a);
            acc_b = __fmaf_rn(q.x, vb.x, acc_b);
            acc_b = __fmaf_rn(q.y, vb.y, acc_b);
            acc_b = __fmaf_rn(q.z, vb.z, acc_b);
            acc_b = __fmaf_rn(q.w, vb.w, acc_b);
        }

        // y(t) partials from B (= r_out(t)), same order as R6 champion
        if (tid >= 448) {
            const int idx = tid - 448;
            const int o = idx & 7, seg = idx >> 3;
            const float* wp = woutT_sh + (seg << 6) * 8 + o;
            const float* rr = B_sh + (seg << 6);
            float e0 = 0.0f, e1 = 0.0f;
#pragma unroll
            for (int hh = 0; hh < 64; hh += 2) {
                e0 = __fmaf_rn(wp[hh << 3],       rr[hh],     e0);
                e1 = __fmaf_rn(wp[(hh + 1) << 3], rr[hh + 1], e1);
            }
            part_a[idx] = e0 + e1;
        }

        // pointwise step t (reference op order, no contraction)
        I = __fadd_rn(__fadd_rn(__fmul_rn(ls, I), fx0), acc_a);
        const float ti0 = __fmul_rn(dtc, (float)t);
        {
            const float notref = (ti0 > __fadd_rn(tlast, tref)) ? 1.0f : 0.0f;
            const float memn = __fmul_rn(__fmul_rn(notref,
                    __fadd_rn(__fmul_rn(lm, mem), __fmul_rn(olm, I))),
                    __fsub_rn(1.0f, s));
            const float snew = (__fsub_rn(memn, 1.0f) > 0.0f) ? 1.0f : 0.0f;
            tlast = __fadd_rn(tlast, __fmul_rn(__fsub_rn(ti0, tlast), snew));
            mem = memn; s = snew;              // r becomes rn (r_out(t))
        }
        // pointwise step t+1; r_in(t+2) elementwise-exact
        const float rn2 = __fadd_rn(__fmul_rn(ldc, rn), __fmul_rn(rgain, s));
        I = __fadd_rn(__fadd_rn(__fmul_rn(ls, I), fx1), acc_b);
        const float ti1 = __fmul_rn(dtc, (float)(t + 1));
        {
            const float notref = (ti1 > __fadd_rn(tlast, tref)) ? 1.0f : 0.0f;
            const float memn = __fmul_rn(__fmul_rn(notref,
                    __fadd_rn(__fmul_rn(lm, mem), __fmul_rn(olm, I))),
                    __fsub_rn(1.0f, s));
            const float snew = (__fsub_rn(memn, 1.0f) > 0.0f) ? 1.0f : 0.0f;
            tlast = __fadd_rn(tlast, __fmul_rn(__fsub_rn(ti1, tlast), snew));
            mem = memn; s = snew;
        }
        r = rn2;                                // carry r_in(t+2)
        fx0 = fx2; fx1 = fx3;

        __syncthreads();   // chains done reading A,B; part_a written

        // y(t) final; publish A = r_in(t+2) (also = r_out(t+1) for y(t+1))
        if (tid < ON) {
            const float* q = part_a + tid;
            float v = ((q[0] + q[8]) + (q[16] + q[24])) +
                      ((q[32] + q[40]) + (q[48] + q[56]));
            out[((size_t)t * BN + b) * ON + tid] = v;
        }
        A_sh[tid] = rn2;
        __syncthreads();   // A ready for y(t+1) partials (and next chain)

        if (tid >= 448) {
            const int idx = tid - 448;
            const int o = idx & 7, seg = idx >> 3;
            const float* wp = woutT_sh + (seg << 6) * 8 + o;
            const float* rr = A_sh + (seg << 6);
            float e0 = 0.0f, e1 = 0.0f;
#pragma unroll
            for (int hh = 0; hh < 64; hh += 2) {
                e0 = __fmaf_rn(wp[hh << 3],       rr[hh],     e0);
                e1 = __fmaf_rn(wp[(hh + 1) << 3], rr[hh + 1], e1);
            }
            part_b[idx] = e0 + e1;
        }
        __syncthreads();   // part_b written

        if (tid < ON) {
            const float* q = part_b + tid;
            float v = ((q[0] + q[8]) + (q[16] + q[24])) +
                      ((q[32] + q[40]) + (q[48] + q[56]));
            out[((size_t)(t + 1) * BN + b) * ON + tid] = v;
        }
        // next iter phase 0 rewrites B (reads of B finished pre-sync2) — safe
    }
}

extern "C" void kernel_launch(void* const* d_in, const int* in_sizes, int n_in,
                              void* d_out, int out_size) {
    const float* x    = (const float*)d_in[0];
    const float* Win  = (const float*)d_in[1];
    const float* Wout = (const float*)d_in[2];
    const float* pin  = (const float*)d_in[3];
    const float* pout = (const float*)d_in[4];
    const float* l    = (const float*)d_in[5];
    float* out = (float*)d_out;

    const float arg_ls = (float)(-0.002 / 0.01);
    const float arg_lm = (float)(-0.002 / 0.02);
    const float arg_ld = (float)(-0.002 / 0.03);
    const float rgain  = (float)(0.002 / 0.03);
    const float dtc    = (float)0.002;
    const float tref   = (float)(5.0 * 0.002);

    fx_kernel<<<(TS * BN) / 64, 512>>>(x, Win);
    wr_kernel<<<HN, 512>>>(pin, pout, l);
    snn_kernel<<<BN, 512>>>(Wout, out, arg_ls, arg_lm, arg_ld, rgain, dtc, tref);
}